// round 2
// baseline (speedup 1.0000x reference)
#include <cuda_runtime.h>
#include <cstdint>

#define N_NODES 100000
#define N_EDGES 1600000

// ---------------- device scratch (no allocations allowed) ----------------
__device__ float g_h[(size_t)N_NODES * 64];     // GEMM output per layer
__device__ float g_y[(size_t)N_NODES * 64];     // aggregated output (next layer input)
__device__ int   g_cnt[N_NODES];                // in-degree counts
__device__ float g_dinv[N_NODES];               // deg^-1/2 (deg includes self loop)
__device__ int   g_offs[N_NODES + 1];           // CSR row offsets (by dst)
__device__ int   g_cursor[N_NODES];             // fill cursors
__device__ int   g_src[N_EDGES];                // CSR column indices (src nodes)
__device__ float g_norm[N_EDGES];               // per-edge norm dinv[src]*dinv[dst]
__device__ int   g_is64;                        // 1 if edge_index is int64

// ---------------- edge index accessors (int32 vs int64, guarded) ----------
__device__ __forceinline__ int load_idx(const void* ei, size_t pos, int is64) {
    long long v;
    if (is64) v = ((const long long*)ei)[pos];
    else      v = ((const int*)ei)[pos];
    if (v < 0) v = 0;
    if (v >= N_NODES) v = N_NODES - 1;
    return (int)v;
}

// Detect dtype: for int64 data (values < 2^31), every odd 32-bit word is 0.
__global__ void detect_k(const int* __restrict__ ei32) {
    int nz = 0;
    for (int i = 0; i < 256; i++) nz += (ei32[2 * i + 1] != 0);
    g_is64 = (nz == 0) ? 1 : 0;
}

// ---------------- setup kernels ----------------
__global__ void init_k() {
    int i = blockIdx.x * blockDim.x + threadIdx.x;
    if (i < N_NODES) { g_cnt[i] = 0; g_cursor[i] = 0; }
}

__global__ void count_k(const void* __restrict__ ei) {
    int e = blockIdx.x * blockDim.x + threadIdx.x;
    if (e < N_EDGES) {
        int d = load_idx(ei, (size_t)N_EDGES + e, g_is64);
        atomicAdd(&g_cnt[d], 1);
    }
}

__global__ void dinv_k() {
    int i = blockIdx.x * blockDim.x + threadIdx.x;
    if (i < N_NODES) g_dinv[i] = rsqrtf((float)g_cnt[i] + 1.0f);
}

// single-block exclusive scan of g_cnt -> g_offs
__global__ void scan_k() {
    __shared__ int ts[1024];
    int t = threadIdx.x;
    const int CH = (N_NODES + 1023) / 1024;   // 98
    int beg = t * CH;
    int end = beg + CH; if (end > N_NODES) end = N_NODES;
    int s = 0;
    for (int i = beg; i < end; i++) s += g_cnt[i];
    ts[t] = s;
    __syncthreads();
    for (int d = 1; d < 1024; d <<= 1) {
        int v = (t >= d) ? ts[t - d] : 0;
        __syncthreads();
        ts[t] += v;
        __syncthreads();
    }
    int run = ts[t] - s;   // exclusive prefix
    for (int i = beg; i < end; i++) { g_offs[i] = run; run += g_cnt[i]; }
    if (t == 1023) g_offs[N_NODES] = ts[1023];
}

__global__ void fill_k(const void* __restrict__ ei) {
    int e = blockIdx.x * blockDim.x + threadIdx.x;
    if (e < N_EDGES) {
        int is64 = g_is64;
        int s = load_idx(ei, e, is64);
        int d = load_idx(ei, (size_t)N_EDGES + e, is64);
        int p = g_offs[d] + atomicAdd(&g_cursor[d], 1);
        g_src[p]  = s;
        g_norm[p] = g_dinv[s] * g_dinv[d];
    }
}

// ---------------- GEMM: h[N,FOUT] = x[N,FIN] @ W[FOUT,FIN]^T ----------------
template<int FIN, int FOUT>
__global__ void gemm_k(const float* __restrict__ x, const float* __restrict__ W,
                       float* __restrict__ h) {
    constexpr int TPR = FOUT / 4;        // threads per row (4 cols each)
    constexpr int RPB = 256 / TPR;       // rows per block
    __shared__ float Ws[FIN * FOUT];     // Ws[k*FOUT + f] = W[f*FIN + k]
    for (int i = threadIdx.x; i < FIN * FOUT; i += 256) {
        int f = i / FIN, k = i % FIN;
        Ws[k * FOUT + f] = W[i];
    }
    __syncthreads();

    int r  = threadIdx.x / TPR;
    int c0 = (threadIdx.x % TPR) * 4;
    int row = blockIdx.x * RPB + r;
    if (row >= N_NODES) return;

    const float4* __restrict__ xr = reinterpret_cast<const float4*>(x + (size_t)row * FIN);
    float a0 = 0.f, a1 = 0.f, a2 = 0.f, a3 = 0.f;
#pragma unroll
    for (int k4 = 0; k4 < FIN / 4; k4++) {
        float4 xv = xr[k4];
        const float4 w0 = *reinterpret_cast<const float4*>(&Ws[(4 * k4 + 0) * FOUT + c0]);
        const float4 w1 = *reinterpret_cast<const float4*>(&Ws[(4 * k4 + 1) * FOUT + c0]);
        const float4 w2 = *reinterpret_cast<const float4*>(&Ws[(4 * k4 + 2) * FOUT + c0]);
        const float4 w3 = *reinterpret_cast<const float4*>(&Ws[(4 * k4 + 3) * FOUT + c0]);
        a0 = fmaf(xv.x, w0.x, a0); a1 = fmaf(xv.x, w0.y, a1);
        a2 = fmaf(xv.x, w0.z, a2); a3 = fmaf(xv.x, w0.w, a3);
        a0 = fmaf(xv.y, w1.x, a0); a1 = fmaf(xv.y, w1.y, a1);
        a2 = fmaf(xv.y, w1.z, a2); a3 = fmaf(xv.y, w1.w, a3);
        a0 = fmaf(xv.z, w2.x, a0); a1 = fmaf(xv.z, w2.y, a1);
        a2 = fmaf(xv.z, w2.z, a2); a3 = fmaf(xv.z, w2.w, a3);
        a0 = fmaf(xv.w, w3.x, a0); a1 = fmaf(xv.w, w3.y, a1);
        a2 = fmaf(xv.w, w3.z, a2); a3 = fmaf(xv.w, w3.w, a3);
    }
    float4 o = make_float4(a0, a1, a2, a3);
    *reinterpret_cast<float4*>(&h[(size_t)row * FOUT + c0]) = o;
}

// ---------------- aggregation: out[i] = relu(sum_j norm*h[src_j] + dinv^2*h[i] + b) ----
// one warp per destination node; lanes span features (F=64 -> lane and lane+32)
template<int F>
__global__ void agg_k(const float* __restrict__ h, const float* __restrict__ b,
                      float* __restrict__ out) {
    int warp = (blockIdx.x * blockDim.x + threadIdx.x) >> 5;
    int lane = threadIdx.x & 31;
    if (warp >= N_NODES) return;
    int node = warp;

    int beg = g_offs[node];
    int end = g_offs[node + 1];

    float a0 = 0.f, a1 = 0.f;
    int j = beg;
    for (; j + 2 <= end; j += 2) {
        int   s0 = g_src[j];
        float w0 = g_norm[j];
        int   s1 = g_src[j + 1];
        float w1 = g_norm[j + 1];
        const float* __restrict__ h0 = h + (size_t)s0 * F;
        const float* __restrict__ h1 = h + (size_t)s1 * F;
        float x00 = h0[lane];
        float x10 = h1[lane];
        float x01 = 0.f, x11 = 0.f;
        if (F == 64) { x01 = h0[lane + 32]; x11 = h1[lane + 32]; }
        a0 = fmaf(w0, x00, a0);
        a0 = fmaf(w1, x10, a0);
        if (F == 64) {
            a1 = fmaf(w0, x01, a1);
            a1 = fmaf(w1, x11, a1);
        }
    }
    if (j < end) {
        int   s0 = g_src[j];
        float w0 = g_norm[j];
        const float* __restrict__ h0 = h + (size_t)s0 * F;
        a0 = fmaf(w0, h0[lane], a0);
        if (F == 64) a1 = fmaf(w0, h0[lane + 32], a1);
    }

    // self loop + bias + relu
    float dv = g_dinv[node];
    float sn = dv * dv;
    const float* __restrict__ hs = h + (size_t)node * F;
    a0 = fmaf(sn, hs[lane], a0) + b[lane];
    out[(size_t)node * F + lane] = fmaxf(a0, 0.f);
    if (F == 64) {
        a1 = fmaf(sn, hs[lane + 32], a1) + b[lane + 32];
        out[(size_t)node * F + lane + 32] = fmaxf(a1, 0.f);
    }
}

// ---------------- launch ----------------
extern "C" void kernel_launch(void* const* d_in, const int* in_sizes, int n_in,
                              void* d_out, int out_size) {
    const float* x  = (const float*)d_in[0];
    const void*  ei = d_in[1];
    const float* W1 = (const float*)d_in[2];
    const float* b1 = (const float*)d_in[3];
    const float* W2 = (const float*)d_in[4];
    const float* b2 = (const float*)d_in[5];
    const float* W3 = (const float*)d_in[6];
    const float* b3 = (const float*)d_in[7];
    float* out = (float*)d_out;

    void *ph = nullptr, *py = nullptr;
    cudaGetSymbolAddress(&ph, g_h);
    cudaGetSymbolAddress(&py, g_y);
    float* h = (float*)ph;
    float* y = (float*)py;

    const int TB = 256;
    // dtype detect + CSR build
    detect_k<<<1, 1>>>((const int*)ei);
    init_k <<<(N_NODES + TB - 1) / TB, TB>>>();
    count_k<<<(N_EDGES + TB - 1) / TB, TB>>>(ei);
    dinv_k <<<(N_NODES + TB - 1) / TB, TB>>>();
    scan_k <<<1, 1024>>>();
    fill_k <<<(N_EDGES + TB - 1) / TB, TB>>>(ei);

    // Layer 1: 32 -> 64
    gemm_k<32, 64><<<N_NODES / 16, TB>>>(x, W1, h);
    agg_k<64>     <<<(N_NODES * 32 + TB - 1) / TB, TB>>>(h, b1, y);
    // Layer 2: 64 -> 64
    gemm_k<64, 64><<<N_NODES / 16, TB>>>(y, W2, h);
    agg_k<64>     <<<(N_NODES * 32 + TB - 1) / TB, TB>>>(h, b2, y);
    // Layer 3: 64 -> 32
    gemm_k<64, 32><<<N_NODES / 32, TB>>>(y, W3, h);
    agg_k<32>     <<<(N_NODES * 32 + TB - 1) / TB, TB>>>(h, b3, out);

    (void)in_sizes; (void)n_in; (void)out_size;
}

// round 3
// speedup vs baseline: 1.0060x; 1.0060x over previous
#include <cuda_runtime.h>
#include <cstdint>

#define N_NODES 100000
#define N_EDGES 1600000

// ---------------- device scratch ----------------
__device__ float g_h[(size_t)N_NODES * 64];
__device__ float g_y[(size_t)N_NODES * 64];
__device__ float g_a[(size_t)N_NODES * 32];     // aggregated input (layer 1)
__device__ int   g_cnt[N_NODES];
__device__ float g_dinv[N_NODES];
__device__ int   g_offs[N_NODES + 1];
__device__ int   g_cursor[N_NODES];
__device__ int2  g_edge[N_EDGES];               // {src, norm-as-int}
__device__ int   g_is64;

// ---------------- edge index accessors (int32 vs int64, guarded) ----------
__device__ __forceinline__ int load_idx(const void* ei, size_t pos, int is64) {
    long long v;
    if (is64) v = ((const long long*)ei)[pos];
    else      v = ((const int*)ei)[pos];
    if (v < 0) v = 0;
    if (v >= N_NODES) v = N_NODES - 1;
    return (int)v;
}

__global__ void detect_k(const int* __restrict__ ei32) {
    int nz = 0;
    for (int i = 0; i < 256; i++) nz += (ei32[2 * i + 1] != 0);
    g_is64 = (nz == 0) ? 1 : 0;
}

__global__ void count_k(const void* __restrict__ ei) {
    int e = blockIdx.x * blockDim.x + threadIdx.x;
    if (e < N_EDGES) {
        int d = load_idx(ei, (size_t)N_EDGES + e, g_is64);
        atomicAdd(&g_cnt[d], 1);
    }
}

__global__ void dinv_k() {
    int i = blockIdx.x * blockDim.x + threadIdx.x;
    if (i < N_NODES) g_dinv[i] = rsqrtf((float)g_cnt[i] + 1.0f);
}

__global__ void scan_k() {
    __shared__ int ts[1024];
    int t = threadIdx.x;
    const int CH = (N_NODES + 1023) / 1024;
    int beg = t * CH;
    int end = beg + CH; if (end > N_NODES) end = N_NODES;
    int s = 0;
    for (int i = beg; i < end; i++) s += g_cnt[i];
    ts[t] = s;
    __syncthreads();
    for (int d = 1; d < 1024; d <<= 1) {
        int v = (t >= d) ? ts[t - d] : 0;
        __syncthreads();
        ts[t] += v;
        __syncthreads();
    }
    int run = ts[t] - s;
    for (int i = beg; i < end; i++) { g_offs[i] = run; run += g_cnt[i]; }
    if (t == 1023) g_offs[N_NODES] = ts[1023];
}

__global__ void fill_k(const void* __restrict__ ei) {
    int e = blockIdx.x * blockDim.x + threadIdx.x;
    if (e < N_EDGES) {
        int is64 = g_is64;
        int s = load_idx(ei, e, is64);
        int d = load_idx(ei, (size_t)N_EDGES + e, is64);
        int p = g_offs[d] + atomicAdd(&g_cursor[d], 1);
        g_edge[p] = make_int2(s, __float_as_int(g_dinv[s] * g_dinv[d]));
    }
}

// ---------------- GEMM: out[N,FOUT] = in[N,FIN] @ W[FOUT,FIN]^T (+bias,relu) ----
template<int FIN, int FOUT, bool BR>
__global__ void gemm_k(const float* __restrict__ x, const float* __restrict__ W,
                       const float* __restrict__ bias, float* __restrict__ h) {
    constexpr int TPR = FOUT / 4;
    constexpr int RPB = 256 / TPR;
    __shared__ float Ws[FIN * FOUT];
    for (int i = threadIdx.x; i < FIN * FOUT; i += 256) {
        int f = i / FIN, k = i % FIN;
        Ws[k * FOUT + f] = W[i];
    }
    __syncthreads();

    int r  = threadIdx.x / TPR;
    int c0 = (threadIdx.x % TPR) * 4;
    int row = blockIdx.x * RPB + r;
    if (row >= N_NODES) return;

    const float4* __restrict__ xr = reinterpret_cast<const float4*>(x + (size_t)row * FIN);
    float a0 = 0.f, a1 = 0.f, a2 = 0.f, a3 = 0.f;
#pragma unroll
    for (int k4 = 0; k4 < FIN / 4; k4++) {
        float4 xv = xr[k4];
        const float4 w0 = *reinterpret_cast<const float4*>(&Ws[(4 * k4 + 0) * FOUT + c0]);
        const float4 w1 = *reinterpret_cast<const float4*>(&Ws[(4 * k4 + 1) * FOUT + c0]);
        const float4 w2 = *reinterpret_cast<const float4*>(&Ws[(4 * k4 + 2) * FOUT + c0]);
        const float4 w3 = *reinterpret_cast<const float4*>(&Ws[(4 * k4 + 3) * FOUT + c0]);
        a0 = fmaf(xv.x, w0.x, a0); a1 = fmaf(xv.x, w0.y, a1);
        a2 = fmaf(xv.x, w0.z, a2); a3 = fmaf(xv.x, w0.w, a3);
        a0 = fmaf(xv.y, w1.x, a0); a1 = fmaf(xv.y, w1.y, a1);
        a2 = fmaf(xv.y, w1.z, a2); a3 = fmaf(xv.y, w1.w, a3);
        a0 = fmaf(xv.z, w2.x, a0); a1 = fmaf(xv.z, w2.y, a1);
        a2 = fmaf(xv.z, w2.z, a2); a3 = fmaf(xv.z, w2.w, a3);
        a0 = fmaf(xv.w, w3.x, a0); a1 = fmaf(xv.w, w3.y, a1);
        a2 = fmaf(xv.w, w3.z, a2); a3 = fmaf(xv.w, w3.w, a3);
    }
    if (BR) {
        a0 = fmaxf(a0 + bias[c0 + 0], 0.f);
        a1 = fmaxf(a1 + bias[c0 + 1], 0.f);
        a2 = fmaxf(a2 + bias[c0 + 2], 0.f);
        a3 = fmaxf(a3 + bias[c0 + 3], 0.f);
    }
    *reinterpret_cast<float4*>(&h[(size_t)row * FOUT + c0]) =
        make_float4(a0, a1, a2, a3);
}

// ---------------- agg F=64: one warp per node, float2 lanes, unroll 4 --------
template<bool BR>
__global__ void agg64_k(const float* __restrict__ h, const float* __restrict__ bias,
                        float* __restrict__ out) {
    int node = (blockIdx.x * blockDim.x + threadIdx.x) >> 5;
    int lane = threadIdx.x & 31;
    if (node >= N_NODES) return;
    const float2* __restrict__ h2 = reinterpret_cast<const float2*>(h);

    int beg = g_offs[node];
    int end = g_offs[node + 1];

    float ax = 0.f, ay = 0.f;
    int j = beg;
    for (; j + 4 <= end; j += 4) {
        int2 e0 = g_edge[j + 0];
        int2 e1 = g_edge[j + 1];
        int2 e2 = g_edge[j + 2];
        int2 e3 = g_edge[j + 3];
        float2 v0 = h2[(size_t)e0.x * 32 + lane];
        float2 v1 = h2[(size_t)e1.x * 32 + lane];
        float2 v2 = h2[(size_t)e2.x * 32 + lane];
        float2 v3 = h2[(size_t)e3.x * 32 + lane];
        float w0 = __int_as_float(e0.y), w1 = __int_as_float(e1.y);
        float w2 = __int_as_float(e2.y), w3 = __int_as_float(e3.y);
        ax = fmaf(w0, v0.x, ax); ay = fmaf(w0, v0.y, ay);
        ax = fmaf(w1, v1.x, ax); ay = fmaf(w1, v1.y, ay);
        ax = fmaf(w2, v2.x, ax); ay = fmaf(w2, v2.y, ay);
        ax = fmaf(w3, v3.x, ax); ay = fmaf(w3, v3.y, ay);
    }
    for (; j < end; j++) {
        int2 e = g_edge[j];
        float w = __int_as_float(e.y);
        float2 v = h2[(size_t)e.x * 32 + lane];
        ax = fmaf(w, v.x, ax); ay = fmaf(w, v.y, ay);
    }

    float dv = g_dinv[node];
    float sn = dv * dv;
    float2 vs = h2[(size_t)node * 32 + lane];
    ax = fmaf(sn, vs.x, ax);
    ay = fmaf(sn, vs.y, ay);
    if (BR) {
        ax = fmaxf(ax + bias[2 * lane + 0], 0.f);
        ay = fmaxf(ay + bias[2 * lane + 1], 0.f);
    }
    reinterpret_cast<float2*>(out)[(size_t)node * 32 + lane] = make_float2(ax, ay);
}

// ---------------- agg F=32: 16 lanes/edge, 2 edges per warp-iter, unroll 2 ----
template<bool BR>
__global__ void agg32_k(const float* __restrict__ h, const float* __restrict__ bias,
                        float* __restrict__ out) {
    int node = (blockIdx.x * blockDim.x + threadIdx.x) >> 5;
    int lane = threadIdx.x & 31;
    if (node >= N_NODES) return;
    int half = lane >> 4;       // 0 or 1: which edge of the pair
    int fl   = lane & 15;       // feature pair index (features 2*fl, 2*fl+1)
    const float2* __restrict__ h2 = reinterpret_cast<const float2*>(h);

    int beg = g_offs[node];
    int end = g_offs[node + 1];

    float ax = 0.f, ay = 0.f;
    int j = beg + half;
    for (; j + 2 < end; j += 4) {
        int2 e0 = g_edge[j];
        int2 e1 = g_edge[j + 2];
        float2 v0 = h2[(size_t)e0.x * 16 + fl];
        float2 v1 = h2[(size_t)e1.x * 16 + fl];
        float w0 = __int_as_float(e0.y), w1 = __int_as_float(e1.y);
        ax = fmaf(w0, v0.x, ax); ay = fmaf(w0, v0.y, ay);
        ax = fmaf(w1, v1.x, ax); ay = fmaf(w1, v1.y, ay);
    }
    if (j < end) {
        int2 e = g_edge[j];
        float w = __int_as_float(e.y);
        float2 v = h2[(size_t)e.x * 16 + fl];
        ax = fmaf(w, v.x, ax); ay = fmaf(w, v.y, ay);
    }

    // combine the two halves
    ax += __shfl_xor_sync(0xFFFFFFFFu, ax, 16);
    ay += __shfl_xor_sync(0xFFFFFFFFu, ay, 16);

    if (half == 0) {
        float dv = g_dinv[node];
        float sn = dv * dv;
        float2 vs = h2[(size_t)node * 16 + fl];
        ax = fmaf(sn, vs.x, ax);
        ay = fmaf(sn, vs.y, ay);
        if (BR) {
            ax = fmaxf(ax + bias[2 * fl + 0], 0.f);
            ay = fmaxf(ay + bias[2 * fl + 1], 0.f);
        }
        reinterpret_cast<float2*>(out)[(size_t)node * 16 + fl] = make_float2(ax, ay);
    }
}

// ---------------- launch ----------------
extern "C" void kernel_launch(void* const* d_in, const int* in_sizes, int n_in,
                              void* d_out, int out_size) {
    const float* x  = (const float*)d_in[0];
    const void*  ei = d_in[1];
    const float* W1 = (const float*)d_in[2];
    const float* b1 = (const float*)d_in[3];
    const float* W2 = (const float*)d_in[4];
    const float* b2 = (const float*)d_in[5];
    const float* W3 = (const float*)d_in[6];
    const float* b3 = (const float*)d_in[7];
    float* out = (float*)d_out;

    void *ph = nullptr, *py = nullptr, *pa = nullptr, *pc = nullptr, *pu = nullptr;
    cudaGetSymbolAddress(&ph, g_h);
    cudaGetSymbolAddress(&py, g_y);
    cudaGetSymbolAddress(&pa, g_a);
    cudaGetSymbolAddress(&pc, g_cnt);
    cudaGetSymbolAddress(&pu, g_cursor);
    float* h = (float*)ph;
    float* y = (float*)py;
    float* a = (float*)pa;

    const int TB = 256;
    const int WGRID = (N_NODES * 32 + TB - 1) / TB;

    // dtype detect + CSR build
    detect_k<<<1, 1>>>((const int*)ei);
    cudaMemsetAsync(pc, 0, N_NODES * sizeof(int));
    cudaMemsetAsync(pu, 0, N_NODES * sizeof(int));
    count_k<<<(N_EDGES + TB - 1) / TB, TB>>>(ei);
    dinv_k <<<(N_NODES + TB - 1) / TB, TB>>>();
    scan_k <<<1, 1024>>>();
    fill_k <<<(N_EDGES + TB - 1) / TB, TB>>>(ei);

    // Layer 1: aggregate input (32-dim) first, then transform+bias+relu
    agg32_k<false><<<WGRID, TB>>>(x, nullptr, a);
    gemm_k<32, 64, true><<<N_NODES / 16, TB>>>(a, W1, b1, y);
    // Layer 2
    gemm_k<64, 64, false><<<N_NODES / 16, TB>>>(y, W2, nullptr, h);
    agg64_k<true><<<WGRID, TB>>>(h, b2, y);
    // Layer 3: transform (64->32) first, then aggregate+bias+relu
    gemm_k<64, 32, false><<<N_NODES / 32, TB>>>(y, W3, nullptr, h);
    agg32_k<true><<<WGRID, TB>>>(h, b3, out);

    (void)in_sizes; (void)n_in; (void)out_size;
}

// round 4
// speedup vs baseline: 1.2185x; 1.2113x over previous
#include <cuda_runtime.h>
#include <cstdint>

#define N_NODES 100000
#define N_EDGES 1600000
#define NBLK 391          // ceil(N_NODES/256)

// ---------------- device scratch ----------------
__device__ float g_h[(size_t)N_NODES * 64];
__device__ float g_y[(size_t)N_NODES * 64];
__device__ float g_a[(size_t)N_NODES * 32];     // aggregated input (layer 1)
__device__ int   g_cnt[N_NODES];
__device__ float g_dinv[N_NODES];
__device__ int   g_offs[N_NODES + 1];
__device__ int   g_cursor[N_NODES];
__device__ int2  g_edge[N_EDGES];               // {src, norm-as-int}
__device__ int   g_bsum[512];                   // per-block count sums
__device__ int   g_boff[512];                   // per-block exclusive offsets
__device__ int   g_is64;

// ---------------- edge index accessors (int32 vs int64, guarded) ----------
__device__ __forceinline__ int load_idx(const void* ei, size_t pos, int is64) {
    long long v;
    if (is64) v = ((const long long*)ei)[pos];
    else      v = ((const int*)ei)[pos];
    if (v < 0) v = 0;
    if (v >= N_NODES) v = N_NODES - 1;
    return (int)v;
}

// int64 data (values < 2^31) has every odd 32-bit word zero.
__global__ void detect_k(const int* __restrict__ ei32) {
    int lane = threadIdx.x;
    int nz = (ei32[2 * lane + 1] != 0);
    unsigned m = __ballot_sync(0xFFFFFFFFu, nz);
    if (lane == 0) g_is64 = (m == 0) ? 1 : 0;
}

__global__ void count_k(const void* __restrict__ ei) {
    int e = blockIdx.x * blockDim.x + threadIdx.x;
    if (e < N_EDGES) {
        int d = load_idx(ei, (size_t)N_EDGES + e, g_is64);
        atomicAdd(&g_cnt[d], 1);
    }
}

__global__ void dinv_k() {
    int i = blockIdx.x * blockDim.x + threadIdx.x;
    if (i < N_NODES) g_dinv[i] = rsqrtf((float)g_cnt[i] + 1.0f);
}

// ---- 3-phase exclusive scan of g_cnt -> g_offs ----
__global__ void bsum_k() {            // NBLK blocks x 256
    __shared__ int ws[8];
    int i = blockIdx.x * 256 + threadIdx.x;
    int v = (i < N_NODES) ? g_cnt[i] : 0;
    int lane = threadIdx.x & 31, wid = threadIdx.x >> 5;
#pragma unroll
    for (int d = 16; d > 0; d >>= 1) v += __shfl_down_sync(0xFFFFFFFFu, v, d);
    if (lane == 0) ws[wid] = v;
    __syncthreads();
    if (wid == 0) {
        int s = (lane < 8) ? ws[lane] : 0;
#pragma unroll
        for (int d = 4; d > 0; d >>= 1) s += __shfl_down_sync(0xFFFFFFFFu, s, d);
        if (lane == 0) g_bsum[blockIdx.x] = s;
    }
}

__global__ void bscan_k() {           // 1 block x 512: scan NBLK sums
    __shared__ int ts[512];
    int t = threadIdx.x;
    int v = (t < NBLK) ? g_bsum[t] : 0;
    ts[t] = v;
    __syncthreads();
    for (int d = 1; d < 512; d <<= 1) {
        int u = (t >= d) ? ts[t - d] : 0;
        __syncthreads();
        ts[t] += u;
        __syncthreads();
    }
    if (t < NBLK) g_boff[t] = ts[t] - v;        // exclusive
    if (t == NBLK - 1) g_offs[N_NODES] = ts[t];
}

__global__ void offs_k() {            // NBLK blocks x 256: local scan + base
    __shared__ int ts[256];
    int i = blockIdx.x * 256 + threadIdx.x;
    int t = threadIdx.x;
    int v = (i < N_NODES) ? g_cnt[i] : 0;
    ts[t] = v;
    __syncthreads();
    for (int d = 1; d < 256; d <<= 1) {
        int u = (t >= d) ? ts[t - d] : 0;
        __syncthreads();
        ts[t] += u;
        __syncthreads();
    }
    if (i < N_NODES) g_offs[i] = g_boff[blockIdx.x] + ts[t] - v;
}

__global__ void fill_k(const void* __restrict__ ei) {
    int e = blockIdx.x * blockDim.x + threadIdx.x;
    if (e < N_EDGES) {
        int is64 = g_is64;
        int s = load_idx(ei, e, is64);
        int d = load_idx(ei, (size_t)N_EDGES + e, is64);
        int p = g_offs[d] + atomicAdd(&g_cursor[d], 1);
        g_edge[p] = make_int2(s, __float_as_int(g_dinv[s] * g_dinv[d]));
    }
}

// ---------------- GEMM: out[N,FOUT] = in[N,FIN] @ W[FOUT,FIN]^T (+bias,relu) ----
template<int FIN, int FOUT, bool BR>
__global__ void gemm_k(const float* __restrict__ x, const float* __restrict__ W,
                       const float* __restrict__ bias, float* __restrict__ h) {
    constexpr int TPR = FOUT / 4;
    constexpr int RPB = 256 / TPR;
    __shared__ float Ws[FIN * FOUT];
    for (int i = threadIdx.x; i < FIN * FOUT; i += 256) {
        int f = i / FIN, k = i % FIN;
        Ws[k * FOUT + f] = W[i];
    }
    __syncthreads();

    int r  = threadIdx.x / TPR;
    int c0 = (threadIdx.x % TPR) * 4;
    int row = blockIdx.x * RPB + r;
    if (row >= N_NODES) return;

    const float4* __restrict__ xr = reinterpret_cast<const float4*>(x + (size_t)row * FIN);
    float a0 = 0.f, a1 = 0.f, a2 = 0.f, a3 = 0.f;
#pragma unroll
    for (int k4 = 0; k4 < FIN / 4; k4++) {
        float4 xv = xr[k4];
        const float4 w0 = *reinterpret_cast<const float4*>(&Ws[(4 * k4 + 0) * FOUT + c0]);
        const float4 w1 = *reinterpret_cast<const float4*>(&Ws[(4 * k4 + 1) * FOUT + c0]);
        const float4 w2 = *reinterpret_cast<const float4*>(&Ws[(4 * k4 + 2) * FOUT + c0]);
        const float4 w3 = *reinterpret_cast<const float4*>(&Ws[(4 * k4 + 3) * FOUT + c0]);
        a0 = fmaf(xv.x, w0.x, a0); a1 = fmaf(xv.x, w0.y, a1);
        a2 = fmaf(xv.x, w0.z, a2); a3 = fmaf(xv.x, w0.w, a3);
        a0 = fmaf(xv.y, w1.x, a0); a1 = fmaf(xv.y, w1.y, a1);
        a2 = fmaf(xv.y, w1.z, a2); a3 = fmaf(xv.y, w1.w, a3);
        a0 = fmaf(xv.z, w2.x, a0); a1 = fmaf(xv.z, w2.y, a1);
        a2 = fmaf(xv.z, w2.z, a2); a3 = fmaf(xv.z, w2.w, a3);
        a0 = fmaf(xv.w, w3.x, a0); a1 = fmaf(xv.w, w3.y, a1);
        a2 = fmaf(xv.w, w3.z, a2); a3 = fmaf(xv.w, w3.w, a3);
    }
    if (BR) {
        a0 = fmaxf(a0 + bias[c0 + 0], 0.f);
        a1 = fmaxf(a1 + bias[c0 + 1], 0.f);
        a2 = fmaxf(a2 + bias[c0 + 2], 0.f);
        a3 = fmaxf(a3 + bias[c0 + 3], 0.f);
    }
    *reinterpret_cast<float4*>(&h[(size_t)row * FOUT + c0]) =
        make_float4(a0, a1, a2, a3);
}

// ---------------- agg F=64: 16 lanes x float4 per edge, 2 edges/iter --------
template<bool BR>
__global__ void agg64_k(const float* __restrict__ h, const float* __restrict__ bias,
                        float* __restrict__ out) {
    int node = (blockIdx.x * blockDim.x + threadIdx.x) >> 5;
    int lane = threadIdx.x & 31;
    if (node >= N_NODES) return;
    int half = lane >> 4;       // which edge of the pair
    int fl   = lane & 15;       // float4 index (features 4*fl .. 4*fl+3)
    const float4* __restrict__ h4 = reinterpret_cast<const float4*>(h);

    int beg = g_offs[node];
    int end = g_offs[node + 1];

    float ax = 0.f, ay = 0.f, az = 0.f, aw = 0.f;
    int j = beg + half;
    for (; j + 2 < end; j += 4) {
        int2 e0 = g_edge[j];
        int2 e1 = g_edge[j + 2];
        float4 v0 = h4[(size_t)e0.x * 16 + fl];
        float4 v1 = h4[(size_t)e1.x * 16 + fl];
        float w0 = __int_as_float(e0.y), w1 = __int_as_float(e1.y);
        ax = fmaf(w0, v0.x, ax); ay = fmaf(w0, v0.y, ay);
        az = fmaf(w0, v0.z, az); aw = fmaf(w0, v0.w, aw);
        ax = fmaf(w1, v1.x, ax); ay = fmaf(w1, v1.y, ay);
        az = fmaf(w1, v1.z, az); aw = fmaf(w1, v1.w, aw);
    }
    if (j < end) {
        int2 e = g_edge[j];
        float w = __int_as_float(e.y);
        float4 v = h4[(size_t)e.x * 16 + fl];
        ax = fmaf(w, v.x, ax); ay = fmaf(w, v.y, ay);
        az = fmaf(w, v.z, az); aw = fmaf(w, v.w, aw);
    }

    ax += __shfl_xor_sync(0xFFFFFFFFu, ax, 16);
    ay += __shfl_xor_sync(0xFFFFFFFFu, ay, 16);
    az += __shfl_xor_sync(0xFFFFFFFFu, az, 16);
    aw += __shfl_xor_sync(0xFFFFFFFFu, aw, 16);

    if (half == 0) {
        float dv = g_dinv[node];
        float sn = dv * dv;
        float4 vs = h4[(size_t)node * 16 + fl];
        ax = fmaf(sn, vs.x, ax); ay = fmaf(sn, vs.y, ay);
        az = fmaf(sn, vs.z, az); aw = fmaf(sn, vs.w, aw);
        if (BR) {
            const float4 bv = reinterpret_cast<const float4*>(bias)[fl];
            ax = fmaxf(ax + bv.x, 0.f); ay = fmaxf(ay + bv.y, 0.f);
            az = fmaxf(az + bv.z, 0.f); aw = fmaxf(aw + bv.w, 0.f);
        }
        reinterpret_cast<float4*>(out)[(size_t)node * 16 + fl] =
            make_float4(ax, ay, az, aw);
    }
}

// ---------------- agg F=32: 8 lanes x float4 per edge, 4 edges/iter ----------
template<bool BR>
__global__ void agg32_k(const float* __restrict__ h, const float* __restrict__ bias,
                        float* __restrict__ out) {
    int node = (blockIdx.x * blockDim.x + threadIdx.x) >> 5;
    int lane = threadIdx.x & 31;
    if (node >= N_NODES) return;
    int q  = lane >> 3;        // which edge of the quad (0..3)
    int fl = lane & 7;         // float4 index (features 4*fl .. 4*fl+3)
    const float4* __restrict__ h4 = reinterpret_cast<const float4*>(h);

    int beg = g_offs[node];
    int end = g_offs[node + 1];

    float ax = 0.f, ay = 0.f, az = 0.f, aw = 0.f;
    int j = beg + q;
    for (; j + 4 < end; j += 8) {
        int2 e0 = g_edge[j];
        int2 e1 = g_edge[j + 4];
        float4 v0 = h4[(size_t)e0.x * 8 + fl];
        float4 v1 = h4[(size_t)e1.x * 8 + fl];
        float w0 = __int_as_float(e0.y), w1 = __int_as_float(e1.y);
        ax = fmaf(w0, v0.x, ax); ay = fmaf(w0, v0.y, ay);
        az = fmaf(w0, v0.z, az); aw = fmaf(w0, v0.w, aw);
        ax = fmaf(w1, v1.x, ax); ay = fmaf(w1, v1.y, ay);
        az = fmaf(w1, v1.z, az); aw = fmaf(w1, v1.w, aw);
    }
    if (j < end) {
        int2 e = g_edge[j];
        float w = __int_as_float(e.y);
        float4 v = h4[(size_t)e.x * 8 + fl];
        ax = fmaf(w, v.x, ax); ay = fmaf(w, v.y, ay);
        az = fmaf(w, v.z, az); aw = fmaf(w, v.w, aw);
    }

    ax += __shfl_xor_sync(0xFFFFFFFFu, ax, 8);
    ay += __shfl_xor_sync(0xFFFFFFFFu, ay, 8);
    az += __shfl_xor_sync(0xFFFFFFFFu, az, 8);
    aw += __shfl_xor_sync(0xFFFFFFFFu, aw, 8);
    ax += __shfl_xor_sync(0xFFFFFFFFu, ax, 16);
    ay += __shfl_xor_sync(0xFFFFFFFFu, ay, 16);
    az += __shfl_xor_sync(0xFFFFFFFFu, az, 16);
    aw += __shfl_xor_sync(0xFFFFFFFFu, aw, 16);

    if (q == 0) {
        float dv = g_dinv[node];
        float sn = dv * dv;
        float4 vs = h4[(size_t)node * 8 + fl];
        ax = fmaf(sn, vs.x, ax); ay = fmaf(sn, vs.y, ay);
        az = fmaf(sn, vs.z, az); aw = fmaf(sn, vs.w, aw);
        if (BR) {
            const float4 bv = reinterpret_cast<const float4*>(bias)[fl];
            ax = fmaxf(ax + bv.x, 0.f); ay = fmaxf(ay + bv.y, 0.f);
            az = fmaxf(az + bv.z, 0.f); aw = fmaxf(aw + bv.w, 0.f);
        }
        reinterpret_cast<float4*>(out)[(size_t)node * 8 + fl] =
            make_float4(ax, ay, az, aw);
    }
}

// ---------------- launch ----------------
extern "C" void kernel_launch(void* const* d_in, const int* in_sizes, int n_in,
                              void* d_out, int out_size) {
    const float* x  = (const float*)d_in[0];
    const void*  ei = d_in[1];
    const float* W1 = (const float*)d_in[2];
    const float* b1 = (const float*)d_in[3];
    const float* W2 = (const float*)d_in[4];
    const float* b2 = (const float*)d_in[5];
    const float* W3 = (const float*)d_in[6];
    const float* b3 = (const float*)d_in[7];
    float* out = (float*)d_out;

    void *ph = nullptr, *py = nullptr, *pa = nullptr, *pc = nullptr, *pu = nullptr;
    cudaGetSymbolAddress(&ph, g_h);
    cudaGetSymbolAddress(&py, g_y);
    cudaGetSymbolAddress(&pa, g_a);
    cudaGetSymbolAddress(&pc, g_cnt);
    cudaGetSymbolAddress(&pu, g_cursor);
    float* h = (float*)ph;
    float* y = (float*)py;
    float* a = (float*)pa;

    const int TB = 256;
    const int WGRID = (N_NODES * 32 + TB - 1) / TB;

    // dtype detect + CSR build
    detect_k<<<1, 32>>>((const int*)ei);
    cudaMemsetAsync(pc, 0, N_NODES * sizeof(int));
    cudaMemsetAsync(pu, 0, N_NODES * sizeof(int));
    count_k<<<(N_EDGES + TB - 1) / TB, TB>>>(ei);
    dinv_k <<<NBLK, TB>>>();
    bsum_k <<<NBLK, TB>>>();
    bscan_k<<<1, 512>>>();
    offs_k <<<NBLK, TB>>>();
    fill_k <<<(N_EDGES + TB - 1) / TB, TB>>>(ei);

    // Layer 1: aggregate input (32-dim) first, then transform+bias+relu
    agg32_k<false><<<WGRID, TB>>>(x, nullptr, a);
    gemm_k<32, 64, true><<<N_NODES / 16, TB>>>(a, W1, b1, y);
    // Layer 2
    gemm_k<64, 64, false><<<N_NODES / 16, TB>>>(y, W2, nullptr, h);
    agg64_k<true><<<WGRID, TB>>>(h, b2, y);
    // Layer 3: transform (64->32) first, then aggregate+bias+relu
    gemm_k<64, 32, false><<<N_NODES / 32, TB>>>(y, W3, nullptr, h);
    agg32_k<true><<<WGRID, TB>>>(h, b3, out);

    (void)in_sizes; (void)n_in; (void)out_size;
}

// round 7
// speedup vs baseline: 1.3430x; 1.1022x over previous
#include <cuda_runtime.h>
#include <cstdint>

#define N_NODES 100000
#define N_EDGES 1600000
#define NBLK 391          // ceil(N_NODES/256)

// ---------------- device scratch ----------------
// g_h doubles as: (a) prescaled 32-dim input buffer for layer 1 (first 12.8MB),
// (b) 64-dim GEMM output for layers 2/3.
__device__ float g_h[(size_t)N_NODES * 64];
__device__ float g_y[(size_t)N_NODES * 64];
__device__ float g_a[(size_t)N_NODES * 32];     // aggregated 32-dim buf
__device__ int   g_cnt[N_NODES];
__device__ float g_dinv[N_NODES];
__device__ int   g_offs[N_NODES + 1];
__device__ int   g_rank[N_EDGES];               // rank of edge within its dst row
__device__ int   g_srcl[N_EDGES];               // CSR src indices
__device__ int   g_bsum[512];
__device__ int   g_boff[512];
__device__ int   g_is64;

// ---------------- edge index accessors (int32 vs int64, guarded) ----------
__device__ __forceinline__ int load_idx(const void* ei, size_t pos, int is64) {
    long long v;
    if (is64) v = ((const long long*)ei)[pos];
    else      v = ((const int*)ei)[pos];
    if (v < 0) v = 0;
    if (v >= N_NODES) v = N_NODES - 1;
    return (int)v;
}

__global__ void detect_k(const int* __restrict__ ei32) {
    int lane = threadIdx.x;
    int nz = (ei32[2 * lane + 1] != 0);
    unsigned m = __ballot_sync(0xFFFFFFFFu, nz);
    if (lane == 0) g_is64 = (m == 0) ? 1 : 0;
}

// count in-degree AND record each edge's rank within its destination row
__global__ void count_k(const void* __restrict__ ei) {
    int e = blockIdx.x * blockDim.x + threadIdx.x;
    if (e < N_EDGES) {
        int d = load_idx(ei, (size_t)N_EDGES + e, g_is64);
        g_rank[e] = atomicAdd(&g_cnt[d], 1);
    }
}

__global__ void dinv_k() {
    int i = blockIdx.x * blockDim.x + threadIdx.x;
    if (i < N_NODES) g_dinv[i] = rsqrtf((float)g_cnt[i] + 1.0f);
}

// ---- 3-phase exclusive scan of g_cnt -> g_offs ----
__global__ void bsum_k() {
    __shared__ int ws[8];
    int i = blockIdx.x * 256 + threadIdx.x;
    int v = (i < N_NODES) ? g_cnt[i] : 0;
    int lane = threadIdx.x & 31, wid = threadIdx.x >> 5;
#pragma unroll
    for (int d = 16; d > 0; d >>= 1) v += __shfl_down_sync(0xFFFFFFFFu, v, d);
    if (lane == 0) ws[wid] = v;
    __syncthreads();
    if (wid == 0) {
        int s = (lane < 8) ? ws[lane] : 0;
#pragma unroll
        for (int d = 4; d > 0; d >>= 1) s += __shfl_down_sync(0xFFFFFFFFu, s, d);
        if (lane == 0) g_bsum[blockIdx.x] = s;
    }
}

__global__ void bscan_k() {
    __shared__ int ts[512];
    int t = threadIdx.x;
    int v = (t < NBLK) ? g_bsum[t] : 0;
    ts[t] = v;
    __syncthreads();
    for (int d = 1; d < 512; d <<= 1) {
        int u = (t >= d) ? ts[t - d] : 0;
        __syncthreads();
        ts[t] += u;
        __syncthreads();
    }
    if (t < NBLK) g_boff[t] = ts[t] - v;
    if (t == NBLK - 1) g_offs[N_NODES] = ts[t];
}

__global__ void offs_k() {
    __shared__ int ts[256];
    int i = blockIdx.x * 256 + threadIdx.x;
    int t = threadIdx.x;
    int v = (i < N_NODES) ? g_cnt[i] : 0;
    ts[t] = v;
    __syncthreads();
    for (int d = 1; d < 256; d <<= 1) {
        int u = (t >= d) ? ts[t - d] : 0;
        __syncthreads();
        ts[t] += u;
        __syncthreads();
    }
    if (i < N_NODES) g_offs[i] = g_boff[blockIdx.x] + ts[t] - v;
}

// scatter src into CSR slots — no atomics (rank precomputed)
__global__ void fill_k(const void* __restrict__ ei) {
    int e = blockIdx.x * blockDim.x + threadIdx.x;
    if (e < N_EDGES) {
        int is64 = g_is64;
        int s = load_idx(ei, e, is64);
        int d = load_idx(ei, (size_t)N_EDGES + e, is64);
        g_srcl[g_offs[d] + g_rank[e]] = s;
    }
}

// x' = dinv[i] * x  (row-scaled input), float4 vectorized
__global__ void scale_k(const float* __restrict__ x, float* __restrict__ xs) {
    int i = blockIdx.x * blockDim.x + threadIdx.x;   // over N_NODES*8 float4s
    if (i < N_NODES * 8) {
        int node = i >> 3;
        float dv = g_dinv[node];
        float4 v = reinterpret_cast<const float4*>(x)[i];
        v.x *= dv; v.y *= dv; v.z *= dv; v.w *= dv;
        reinterpret_cast<float4*>(xs)[i] = v;
    }
}

// ---------------- GEMM: out[N,FOUT] = in[N,FIN] @ W^T, optional bias+relu or dinv-scale
template<int FIN, int FOUT, bool BR, bool SCALE>
__global__ void gemm_k(const float* __restrict__ x, const float* __restrict__ W,
                       const float* __restrict__ bias, float* __restrict__ h) {
    constexpr int TPR = FOUT / 4;
    constexpr int RPB = 256 / TPR;
    __shared__ float Ws[FIN * FOUT];
    for (int i = threadIdx.x; i < FIN * FOUT; i += 256) {
        int f = i / FIN, k = i % FIN;
        Ws[k * FOUT + f] = W[i];
    }
    __syncthreads();

    int r  = threadIdx.x / TPR;
    int c0 = (threadIdx.x % TPR) * 4;
    int row = blockIdx.x * RPB + r;
    if (row >= N_NODES) return;

    const float4* __restrict__ xr = reinterpret_cast<const float4*>(x + (size_t)row * FIN);
    float a0 = 0.f, a1 = 0.f, a2 = 0.f, a3 = 0.f;
#pragma unroll
    for (int k4 = 0; k4 < FIN / 4; k4++) {
        float4 xv = xr[k4];
        const float4 w0 = *reinterpret_cast<const float4*>(&Ws[(4 * k4 + 0) * FOUT + c0]);
        const float4 w1 = *reinterpret_cast<const float4*>(&Ws[(4 * k4 + 1) * FOUT + c0]);
        const float4 w2 = *reinterpret_cast<const float4*>(&Ws[(4 * k4 + 2) * FOUT + c0]);
        const float4 w3 = *reinterpret_cast<const float4*>(&Ws[(4 * k4 + 3) * FOUT + c0]);
        a0 = fmaf(xv.x, w0.x, a0); a1 = fmaf(xv.x, w0.y, a1);
        a2 = fmaf(xv.x, w0.z, a2); a3 = fmaf(xv.x, w0.w, a3);
        a0 = fmaf(xv.y, w1.x, a0); a1 = fmaf(xv.y, w1.y, a1);
        a2 = fmaf(xv.y, w1.z, a2); a3 = fmaf(xv.y, w1.w, a3);
        a0 = fmaf(xv.z, w2.x, a0); a1 = fmaf(xv.z, w2.y, a1);
        a2 = fmaf(xv.z, w2.z, a2); a3 = fmaf(xv.z, w2.w, a3);
        a0 = fmaf(xv.w, w3.x, a0); a1 = fmaf(xv.w, w3.y, a1);
        a2 = fmaf(xv.w, w3.z, a2); a3 = fmaf(xv.w, w3.w, a3);
    }
    if (BR) {
        a0 = fmaxf(a0 + bias[c0 + 0], 0.f);
        a1 = fmaxf(a1 + bias[c0 + 1], 0.f);
        a2 = fmaxf(a2 + bias[c0 + 2], 0.f);
        a3 = fmaxf(a3 + bias[c0 + 3], 0.f);
    }
    if (SCALE) {
        float dv = g_dinv[row];
        a0 *= dv; a1 *= dv; a2 *= dv; a3 *= dv;
    }
    *reinterpret_cast<float4*>(&h[(size_t)row * FOUT + c0]) =
        make_float4(a0, a1, a2, a3);
}

// ---------------- agg F=64: out[d] = post( dinv[d]*(sum h'[s] + h'[d]) ) ----
// 16 lanes x float4 per edge, 2 edges per warp-iteration
template<bool BR>
__global__ void agg64_k(const float* __restrict__ h, const float* __restrict__ bias,
                        float* __restrict__ out) {
    int node = (blockIdx.x * blockDim.x + threadIdx.x) >> 5;
    int lane = threadIdx.x & 31;
    if (node >= N_NODES) return;
    int half = lane >> 4;
    int fl   = lane & 15;
    const float4* __restrict__ h4 = reinterpret_cast<const float4*>(h);

    int beg = g_offs[node];
    int end = g_offs[node + 1];

    float ax = 0.f, ay = 0.f, az = 0.f, aw = 0.f;
    int j = beg + half;
    for (; j + 2 < end; j += 4) {
        int s0 = g_srcl[j];
        int s1 = g_srcl[j + 2];
        float4 v0 = h4[(size_t)s0 * 16 + fl];
        float4 v1 = h4[(size_t)s1 * 16 + fl];
        ax += v0.x + v1.x; ay += v0.y + v1.y;
        az += v0.z + v1.z; aw += v0.w + v1.w;
    }
    if (j < end) {
        int s = g_srcl[j];
        float4 v = h4[(size_t)s * 16 + fl];
        ax += v.x; ay += v.y; az += v.z; aw += v.w;
    }

    ax += __shfl_xor_sync(0xFFFFFFFFu, ax, 16);
    ay += __shfl_xor_sync(0xFFFFFFFFu, ay, 16);
    az += __shfl_xor_sync(0xFFFFFFFFu, az, 16);
    aw += __shfl_xor_sync(0xFFFFFFFFu, aw, 16);

    if (half == 0) {
        float dv = g_dinv[node];
        float4 vs = h4[(size_t)node * 16 + fl];
        ax = (ax + vs.x) * dv; ay = (ay + vs.y) * dv;
        az = (az + vs.z) * dv; aw = (aw + vs.w) * dv;
        if (BR) {
            const float4 bv = reinterpret_cast<const float4*>(bias)[fl];
            ax = fmaxf(ax + bv.x, 0.f); ay = fmaxf(ay + bv.y, 0.f);
            az = fmaxf(az + bv.z, 0.f); aw = fmaxf(aw + bv.w, 0.f);
        }
        reinterpret_cast<float4*>(out)[(size_t)node * 16 + fl] =
            make_float4(ax, ay, az, aw);
    }
}

// ---------------- agg F=32: 8 lanes x float4 per edge, 4 edges per warp-iter --
template<bool BR>
__global__ void agg32_k(const float* __restrict__ h, const float* __restrict__ bias,
                        float* __restrict__ out) {
    int node = (blockIdx.x * blockDim.x + threadIdx.x) >> 5;
    int lane = threadIdx.x & 31;
    if (node >= N_NODES) return;
    int q  = lane >> 3;
    int fl = lane & 7;
    const float4* __restrict__ h4 = reinterpret_cast<const float4*>(h);

    int beg = g_offs[node];
    int end = g_offs[node + 1];

    float ax = 0.f, ay = 0.f, az = 0.f, aw = 0.f;
    int j = beg + q;
    for (; j + 4 < end; j += 8) {
        int s0 = g_srcl[j];
        int s1 = g_srcl[j + 4];
        float4 v0 = h4[(size_t)s0 * 8 + fl];
        float4 v1 = h4[(size_t)s1 * 8 + fl];
        ax += v0.x + v1.x; ay += v0.y + v1.y;
        az += v0.z + v1.z; aw += v0.w + v1.w;
    }
    if (j < end) {
        int s = g_srcl[j];
        float4 v = h4[(size_t)s * 8 + fl];
        ax += v.x; ay += v.y; az += v.z; aw += v.w;
    }

    ax += __shfl_xor_sync(0xFFFFFFFFu, ax, 8);
    ay += __shfl_xor_sync(0xFFFFFFFFu, ay, 8);
    az += __shfl_xor_sync(0xFFFFFFFFu, az, 8);
    aw += __shfl_xor_sync(0xFFFFFFFFu, aw, 8);
    ax += __shfl_xor_sync(0xFFFFFFFFu, ax, 16);
    ay += __shfl_xor_sync(0xFFFFFFFFu, ay, 16);
    az += __shfl_xor_sync(0xFFFFFFFFu, az, 16);
    aw += __shfl_xor_sync(0xFFFFFFFFu, aw, 16);

    if (q == 0) {
        float dv = g_dinv[node];
        float4 vs = h4[(size_t)node * 8 + fl];
        ax = (ax + vs.x) * dv; ay = (ay + vs.y) * dv;
        az = (az + vs.z) * dv; aw = (aw + vs.w) * dv;
        if (BR) {
            const float4 bv = reinterpret_cast<const float4*>(bias)[fl];
            ax = fmaxf(ax + bv.x, 0.f); ay = fmaxf(ay + bv.y, 0.f);
            az = fmaxf(az + bv.z, 0.f); aw = fmaxf(aw + bv.w, 0.f);
        }
        reinterpret_cast<float4*>(out)[(size_t)node * 8 + fl] =
            make_float4(ax, ay, az, aw);
    }
}

// ---------------- launch ----------------
extern "C" void kernel_launch(void* const* d_in, const int* in_sizes, int n_in,
                              void* d_out, int out_size) {
    const float* x  = (const float*)d_in[0];
    const void*  ei = d_in[1];
    const float* W1 = (const float*)d_in[2];
    const float* b1 = (const float*)d_in[3];
    const float* W2 = (const float*)d_in[4];
    const float* b2 = (const float*)d_in[5];
    const float* W3 = (const float*)d_in[6];
    const float* b3 = (const float*)d_in[7];
    float* out = (float*)d_out;

    void *ph, *py, *pa, *pc;
    cudaGetSymbolAddress(&ph, g_h);
    cudaGetSymbolAddress(&py, g_y);
    cudaGetSymbolAddress(&pa, g_a);
    cudaGetSymbolAddress(&pc, g_cnt);
    float* h  = (float*)ph;
    float* y  = (float*)py;
    float* a  = (float*)pa;
    float* xs = h;   // layer-1 prescaled input lives in g_h (idle until layer 2)

    const int TB = 256;
    const int WGRID = (N_NODES * 32 + TB - 1) / TB;
    const int EGRID = (N_EDGES + TB - 1) / TB;

    // dtype detect + CSR build (rank-based, no cursor atomics)
    detect_k<<<1, 32>>>((const int*)ei);
    cudaMemsetAsync(pc, 0, N_NODES * sizeof(int));
    count_k<<<EGRID, TB>>>(ei);
    dinv_k <<<NBLK, TB>>>();
    bsum_k <<<NBLK, TB>>>();
    bscan_k<<<1, 512>>>();
    offs_k <<<NBLK, TB>>>();
    fill_k <<<EGRID, TB>>>(ei);

    // Layer 1: x' = dinv*x (in g_h); a = dinv*(sum x'[s] + x'[d]); y1 = relu(a@W1^T + b1)
    scale_k<<<(N_NODES * 8 + TB - 1) / TB, TB>>>(x, xs);
    agg32_k<false><<<WGRID, TB>>>(xs, nullptr, a);
    gemm_k<32, 64, true, false><<<N_NODES / 16, TB>>>(a, W1, b1, y);
    // Layer 2: h' = dinv*(y1@W2^T); y2 = relu(dinv*(sum h'[s] + h'[d]) + b2)
    gemm_k<64, 64, false, true><<<N_NODES / 16, TB>>>(y, W2, nullptr, h);
    agg64_k<true><<<WGRID, TB>>>(h, b2, y);
    // Layer 3: h' = dinv*(y2@W3^T); out = relu(dinv*(sum h'[s] + h'[d]) + b3)
    gemm_k<64, 32, false, true><<<N_NODES / 32, TB>>>(y, W3, nullptr, h);
    agg32_k<true><<<WGRID, TB>>>(h, b3, out);

    (void)in_sizes; (void)n_in; (void)out_size;
}